// round 8
// baseline (speedup 1.0000x reference)
#include <cuda_runtime.h>
#include <cuda_bf16.h>
#include <cstddef>

#define T_STEPS 512
#define B_SIZE  512
#define NIN     64
#define H1      100
#define H2      50
#define H3      25
#define M_ROWS  (T_STEPS * B_SIZE)   // 262144

// Scratch: static device globals.
__device__ float g_xg[(size_t)M_ROWS * 4 * H1];   // reused per layer
__device__ float g_h [(size_t)M_ROWS * H1];       // reused per layer

__device__ __forceinline__ float sigf(float x) {
    return 1.0f / (1.0f + __expf(-x));
}
__device__ __forceinline__ float tanhf_(float x) {
    return 1.0f - 2.0f / (__expf(2.0f * x) + 1.0f);
}

// ---- packed fp32x2 helpers (sm_100+) --------------------------------------
__device__ __forceinline__ unsigned long long ffma2(unsigned long long a,
                                                    unsigned long long b,
                                                    unsigned long long c) {
    unsigned long long d;
    asm("fma.rn.f32x2 %0, %1, %2, %3;" : "=l"(d) : "l"(a), "l"(b), "l"(c));
    return d;
}
__device__ __forceinline__ float sum2(unsigned long long a) {
    float lo, hi;
    asm("mov.b64 {%0, %1}, %2;" : "=f"(lo), "=f"(hi) : "l"(a));
    return lo + hi;
}
__device__ __forceinline__ unsigned long long pack2(float lo, float hi) {
    unsigned long long d;
    asm("mov.b64 %0, {%1, %2};" : "=l"(d) : "f"(lo), "f"(hi));
    return d;
}
union F4U2 { float4 f; unsigned long long u[2]; };

// ---------------------------------------------------------------------------
// xg GEMM (R5 version, known-passing): g_xg[M,N] = inp[M,K] @ w[N,K]^T + biases
// inp == nullptr -> read from g_h (layers 2, 3).
// TM = 128 rows/CTA, 256 threads, W streamed in 64-row tiles, 8x4 thread tile,
// packed f32x2 FMA over k-pairs.
// ---------------------------------------------------------------------------
template <int K, int N>
__global__ void __launch_bounds__(256, 2)
xg_gemm(const float* __restrict__ inp_,
        const float* __restrict__ w,
        const float* __restrict__ bia,
        const float* __restrict__ bib)
{
    const float* inp = (inp_ != nullptr) ? inp_ : (const float*)g_h;

    constexpr int KP    = (K + 3) & ~3;
    constexpr int TM    = 128;
    constexpr int NFULL = (N / 64) * 64;

    extern __shared__ float sm[];
    float* a_s = sm;             // TM * KP
    float* w_s = sm + TM * KP;   // 64 * KP

    const int tid = threadIdx.x;
    const size_t m0 = (size_t)blockIdx.x * TM;

    for (int idx = tid; idx < TM * KP; idx += 256) {
        int r = idx / KP, k = idx - r * KP;
        a_s[idx] = (k < K) ? inp[(m0 + r) * K + k] : 0.0f;
    }

    const int tr = tid >> 4;    // 0..15
    const int tc = tid & 15;    // 0..15
    const int r0 = tr * 8;

    // full 64-column blocks
    for (int nc = 0; nc < NFULL; nc += 64) {
        __syncthreads();
        for (int idx = tid; idx < 64 * KP; idx += 256) {
            int n = idx / KP, k = idx - n * KP;
            w_s[idx] = (k < K) ? w[(nc + n) * K + k] : 0.0f;
        }
        __syncthreads();

        unsigned long long acc2[8][4];
        #pragma unroll
        for (int u = 0; u < 8; ++u)
            #pragma unroll
            for (int v = 0; v < 4; ++v) acc2[u][v] = 0ull;

        for (int k = 0; k < KP; k += 4) {
            F4U2 wv[4];
            #pragma unroll
            for (int v = 0; v < 4; ++v)
                wv[v] = *(const F4U2*)&w_s[(tc + v * 16) * KP + k];
            #pragma unroll
            for (int u = 0; u < 8; ++u) {
                F4U2 av = *(const F4U2*)&a_s[(r0 + u) * KP + k];
                #pragma unroll
                for (int v = 0; v < 4; ++v) {
                    acc2[u][v] = ffma2(av.u[0], wv[v].u[0], acc2[u][v]);
                    acc2[u][v] = ffma2(av.u[1], wv[v].u[1], acc2[u][v]);
                }
            }
        }

        #pragma unroll
        for (int v = 0; v < 4; ++v) {
            int n = nc + tc + v * 16;
            float bb = bia[n] + bib[n];
            #pragma unroll
            for (int u = 0; u < 8; ++u)
                g_xg[(m0 + r0 + u) * N + n] = sum2(acc2[u][v]) + bb;
        }
    }

    // remainder columns, 16 at a time
    for (int nc = NFULL; nc < N; nc += 16) {
        __syncthreads();
        for (int idx = tid; idx < 16 * KP; idx += 256) {
            int n = idx / KP, k = idx - n * KP;
            int col = nc + n; if (col >= N) col = N - 1;
            w_s[idx] = (k < K) ? w[col * K + k] : 0.0f;
        }
        __syncthreads();

        unsigned long long acc8[8];
        #pragma unroll
        for (int u = 0; u < 8; ++u) acc8[u] = 0ull;

        for (int k = 0; k < KP; k += 4) {
            F4U2 wv = *(const F4U2*)&w_s[tc * KP + k];
            #pragma unroll
            for (int u = 0; u < 8; ++u) {
                F4U2 av = *(const F4U2*)&a_s[(r0 + u) * KP + k];
                acc8[u] = ffma2(av.u[0], wv.u[0], acc8[u]);
                acc8[u] = ffma2(av.u[1], wv.u[1], acc8[u]);
            }
        }

        int col = nc + tc;
        if (col < N) {
            float bb = bia[col] + bib[col];
            #pragma unroll
            for (int u = 0; u < 8; ++u)
                g_xg[(m0 + r0 + u) * N + col] = sum2(acc8[u]) + bb;
        }
    }
}

// ---------------------------------------------------------------------------
// LSTM scan with k-split: 2 threads per gate row (each owns half the k range),
// W_hh half-row in registers (packed pairs), BT=4 batches per CTA.
// Block = 2*4H threads (2x warps vs R5 -> latency hiding); partial sums
// combined in the epilogue via one float2 load per gate.
// ---------------------------------------------------------------------------
template <int H, int KPAD, int BLK>
__global__ void __launch_bounds__(BLK, 1)
lstm_scan(const float* __restrict__ whh)
{
    constexpr int G  = 4 * H;
    constexpr int BT = 4;
    constexpr int KH = KPAD / 2;          // k range per half (multiple of 4)

    __shared__ float h_s[BT * KPAD];
    __shared__ float g_s[BT * G * 2];     // [b][gate_row][half] partials

    const int tid = threadIdx.x;
    const int b0  = blockIdx.x * BT;

    const bool mv   = (tid < 2 * G);
    const int  half = mv ? (tid / G) : 0;
    const int  j    = mv ? (tid - half * G) : 0;
    const int  kbase = half * KH;

    // W half-row -> registers, packed (k, k+1)
    unsigned long long wreg[KH / 2];
    if (mv) {
        const float* wr = whh + j * H;
        #pragma unroll
        for (int kk = 0; kk < KH; kk += 2) {
            int k0 = kbase + kk, k1 = k0 + 1;
            float a = (k0 < H) ? wr[k0] : 0.0f;
            float b = (k1 < H) ? wr[k1] : 0.0f;
            wreg[kk / 2] = pack2(a, b);
        }
    }
    for (int i = tid; i < BT * KPAD; i += BLK) h_s[i] = 0.0f;

    const bool ep = (tid < BT * H);
    const int  eb = ep ? (tid / H) : 0;
    const int  ej = tid - eb * H;
    float c = 0.0f;

    __syncthreads();

    float nxt[BT];
    if (mv && half == 0) {
        const float* xp = g_xg + (size_t)b0 * G + j;
        #pragma unroll
        for (int b = 0; b < BT; ++b) nxt[b] = xp[b * G];
    }

    for (int t = 0; t < T_STEPS; ++t) {
        if (mv) {
            unsigned long long acc2[BT];
            #pragma unroll
            for (int b = 0; b < BT; ++b)
                acc2[b] = (half == 0) ? pack2(nxt[b], 0.0f) : 0ull;

            if (half == 0 && t + 1 < T_STEPS) {
                const float* xq = g_xg + ((size_t)(t + 1) * B_SIZE + b0) * G + j;
                #pragma unroll
                for (int b = 0; b < BT; ++b) nxt[b] = xq[b * G];
            }

            #pragma unroll
            for (int kk = 0; kk < KH; kk += 4) {
                #pragma unroll
                for (int b = 0; b < BT; ++b) {
                    F4U2 hv = *(const F4U2*)&h_s[b * KPAD + kbase + kk];
                    acc2[b] = ffma2(wreg[kk / 2],     hv.u[0], acc2[b]);
                    acc2[b] = ffma2(wreg[kk / 2 + 1], hv.u[1], acc2[b]);
                }
            }
            #pragma unroll
            for (int b = 0; b < BT; ++b)
                g_s[(b * G + j) * 2 + half] = sum2(acc2[b]);
        }
        __syncthreads();

        if (ep) {
            float2 p;
            p = *(const float2*)&g_s[(eb * G + ej) * 2];
            float gi = p.x + p.y;
            p = *(const float2*)&g_s[(eb * G + H + ej) * 2];
            float gf = p.x + p.y;
            p = *(const float2*)&g_s[(eb * G + 2 * H + ej) * 2];
            float gg = p.x + p.y;
            p = *(const float2*)&g_s[(eb * G + 3 * H + ej) * 2];
            float go = p.x + p.y;

            float cn = sigf(gf) * c + sigf(gi) * tanhf_(gg);
            c = cn;
            float hv = sigf(go) * tanhf_(cn);
            h_s[eb * KPAD + ej] = hv;
            g_h[((size_t)t * B_SIZE + b0 + eb) * H + ej] = hv;
        }
        __syncthreads();
    }
}

// ---------------------------------------------------------------------------
// Final linear: out[m] = sum_k g_h[m][k] * w[k] + b, K = 25
// ---------------------------------------------------------------------------
__global__ void linear_out(const float* __restrict__ wl,
                           const float* __restrict__ bl,
                           float* __restrict__ out)
{
    __shared__ float sm[256 * H3];
    __shared__ float wsh[H3];
    const int tid = threadIdx.x;
    const size_t base = (size_t)blockIdx.x * 256 * H3;

    for (int idx = tid; idx < 256 * H3; idx += 256) sm[idx] = g_h[base + idx];
    if (tid < H3) wsh[tid] = wl[tid];
    __syncthreads();

    float a = bl[0];
    #pragma unroll
    for (int k = 0; k < H3; ++k) a = fmaf(sm[tid * H3 + k], wsh[k], a);
    out[(size_t)blockIdx.x * 256 + tid] = a;
}

// ---------------------------------------------------------------------------
extern "C" void kernel_launch(void* const* d_in, const int* in_sizes, int n_in,
                              void* d_out, int out_size)
{
    const float* x     = (const float*)d_in[0];
    const float* w_ih1 = (const float*)d_in[1];
    const float* w_hh1 = (const float*)d_in[2];
    const float* b_ih1 = (const float*)d_in[3];
    const float* b_hh1 = (const float*)d_in[4];
    const float* w_ih2 = (const float*)d_in[5];
    const float* w_hh2 = (const float*)d_in[6];
    const float* b_ih2 = (const float*)d_in[7];
    const float* b_hh2 = (const float*)d_in[8];
    const float* w_ih3 = (const float*)d_in[9];
    const float* w_hh3 = (const float*)d_in[10];
    const float* b_ih3 = (const float*)d_in[11];
    const float* b_hh3 = (const float*)d_in[12];
    const float* w_lin = (const float*)d_in[13];
    const float* b_lin = (const float*)d_in[14];
    float* out = (float*)d_out;

    // GEMM dynamic smem sizes (floats * 4)
    const int SZ_G1 = (128 + 64) * 64  * 4;   // 49152
    const int SZ_G2 = (128 + 64) * 100 * 4;   // 76800
    const int SZ_G3 = (128 + 64) * 52  * 4;   // 39936

    cudaFuncSetAttribute(xg_gemm<64, 400>,  cudaFuncAttributeMaxDynamicSharedMemorySize, SZ_G1);
    cudaFuncSetAttribute(xg_gemm<100, 200>, cudaFuncAttributeMaxDynamicSharedMemorySize, SZ_G2);
    cudaFuncSetAttribute(xg_gemm<50, 100>,  cudaFuncAttributeMaxDynamicSharedMemorySize, SZ_G3);

    const int GRID_M = M_ROWS / 128;  // 2048
    const int GRID_B = B_SIZE / 4;    // 128

    // Layer 1  (H=100: KPAD=104, KH=52; block = 2*400 = 800 = 25 warps)
    xg_gemm<64, 400><<<GRID_M, 256, SZ_G1>>>(x, w_ih1, b_ih1, b_hh1);
    lstm_scan<100, 104, 800><<<GRID_B, 800>>>(w_hh1);
    // Layer 2  (H=50: KPAD=56, KH=28; block = 416, 400 active)
    xg_gemm<100, 200><<<GRID_M, 256, SZ_G2>>>(nullptr, w_ih2, b_ih2, b_hh2);
    lstm_scan<50, 56, 416><<<GRID_B, 416>>>(w_hh2);
    // Layer 3  (H=25: KPAD=32, KH=16; block = 224, 200 active)
    xg_gemm<50, 100><<<GRID_M, 256, SZ_G3>>>(nullptr, w_ih3, b_ih3, b_hh3);
    lstm_scan<25, 32, 224><<<GRID_B, 224>>>(w_hh3);
    // Output
    linear_out<<<M_ROWS / 256, 256>>>(w_lin, b_lin, out);
}

// round 10
// speedup vs baseline: 1.4797x; 1.4797x over previous
#include <cuda_runtime.h>
#include <cuda_bf16.h>
#include <cstddef>

#define T_STEPS 512
#define B_SIZE  512
#define NIN     64
#define H1      100
#define H2      50
#define H3      25
#define M_ROWS  (T_STEPS * B_SIZE)   // 262144

// Scratch: static device globals.
__device__ float g_xg[(size_t)M_ROWS * 4 * H1];   // reused per layer
__device__ float g_h [(size_t)M_ROWS * H1];       // reused per layer

__device__ __forceinline__ float sigf(float x) {
    return 1.0f / (1.0f + __expf(-x));
}
__device__ __forceinline__ float tanhf_(float x) {
    return 1.0f - 2.0f / (__expf(2.0f * x) + 1.0f);
}

// ---- packed fp32x2 helpers (sm_100+) --------------------------------------
__device__ __forceinline__ unsigned long long ffma2(unsigned long long a,
                                                    unsigned long long b,
                                                    unsigned long long c) {
    unsigned long long d;
    asm("fma.rn.f32x2 %0, %1, %2, %3;" : "=l"(d) : "l"(a), "l"(b), "l"(c));
    return d;
}
__device__ __forceinline__ float sum2(unsigned long long a) {
    float lo, hi;
    asm("mov.b64 {%0, %1}, %2;" : "=f"(lo), "=f"(hi) : "l"(a));
    return lo + hi;
}
__device__ __forceinline__ unsigned long long pack2(float lo, float hi) {
    unsigned long long d;
    asm("mov.b64 %0, {%1, %2};" : "=l"(d) : "f"(lo), "f"(hi));
    return d;
}
union F4U2 { float4 f; unsigned long long u[2]; };

// KP chooser: round K up to a multiple of 4, then ensure KP/4 is ODD so that
// smem rows at stride KP map tc -> distinct bank quads (conflict-free LDS.128).
template <int K>
struct KPad {
    static constexpr int KP0 = (K + 3) & ~3;
    static constexpr int KP  = ((KP0 / 4) % 2 == 0) ? (KP0 + 4) : KP0;
};

// ---------------------------------------------------------------------------
// xg GEMM (R5 structure, known-passing + bank-conflict-free padding):
// g_xg[M, N] = inp[M, K] @ w[N, K]^T + bia[N] + bib[N]
// inp == nullptr -> read from g_h (layers 2, 3).
// TM = 128 rows/CTA, 256 threads, W streamed in 64-row tiles, 8x4 tile,
// packed f32x2 FMA over k-pairs.
// ---------------------------------------------------------------------------
template <int K, int N>
__global__ void __launch_bounds__(256, 2)
xg_gemm(const float* __restrict__ inp_,
        const float* __restrict__ w,
        const float* __restrict__ bia,
        const float* __restrict__ bib)
{
    const float* inp = (inp_ != nullptr) ? inp_ : (const float*)g_h;

    constexpr int KP    = KPad<K>::KP;
    constexpr int TM    = 128;
    constexpr int NFULL = (N / 64) * 64;

    extern __shared__ float sm[];
    float* a_s = sm;             // TM * KP
    float* w_s = sm + TM * KP;   // 64 * KP

    const int tid = threadIdx.x;
    const size_t m0 = (size_t)blockIdx.x * TM;

    for (int idx = tid; idx < TM * KP; idx += 256) {
        int r = idx / KP, k = idx - r * KP;
        a_s[idx] = (k < K) ? inp[(m0 + r) * K + k] : 0.0f;
    }

    const int tr = tid >> 4;    // 0..15
    const int tc = tid & 15;    // 0..15
    const int r0 = tr * 8;

    // full 64-column blocks
    for (int nc = 0; nc < NFULL; nc += 64) {
        __syncthreads();
        for (int idx = tid; idx < 64 * KP; idx += 256) {
            int n = idx / KP, k = idx - n * KP;
            w_s[idx] = (k < K) ? w[(nc + n) * K + k] : 0.0f;
        }
        __syncthreads();

        unsigned long long acc2[8][4];
        #pragma unroll
        for (int u = 0; u < 8; ++u)
            #pragma unroll
            for (int v = 0; v < 4; ++v) acc2[u][v] = 0ull;

        for (int k = 0; k < KP; k += 4) {
            F4U2 wv[4];
            #pragma unroll
            for (int v = 0; v < 4; ++v)
                wv[v] = *(const F4U2*)&w_s[(tc + v * 16) * KP + k];
            #pragma unroll
            for (int u = 0; u < 8; ++u) {
                F4U2 av = *(const F4U2*)&a_s[(r0 + u) * KP + k];
                #pragma unroll
                for (int v = 0; v < 4; ++v) {
                    acc2[u][v] = ffma2(av.u[0], wv[v].u[0], acc2[u][v]);
                    acc2[u][v] = ffma2(av.u[1], wv[v].u[1], acc2[u][v]);
                }
            }
        }

        #pragma unroll
        for (int v = 0; v < 4; ++v) {
            int n = nc + tc + v * 16;
            float bb = bia[n] + bib[n];
            #pragma unroll
            for (int u = 0; u < 8; ++u)
                g_xg[(m0 + r0 + u) * N + n] = sum2(acc2[u][v]) + bb;
        }
    }

    // remainder columns, 16 at a time
    for (int nc = NFULL; nc < N; nc += 16) {
        __syncthreads();
        for (int idx = tid; idx < 16 * KP; idx += 256) {
            int n = idx / KP, k = idx - n * KP;
            int col = nc + n; if (col >= N) col = N - 1;
            w_s[idx] = (k < K) ? w[col * K + k] : 0.0f;
        }
        __syncthreads();

        unsigned long long acc8[8];
        #pragma unroll
        for (int u = 0; u < 8; ++u) acc8[u] = 0ull;

        for (int k = 0; k < KP; k += 4) {
            F4U2 wv = *(const F4U2*)&w_s[tc * KP + k];
            #pragma unroll
            for (int u = 0; u < 8; ++u) {
                F4U2 av = *(const F4U2*)&a_s[(r0 + u) * KP + k];
                acc8[u] = ffma2(av.u[0], wv.u[0], acc8[u]);
                acc8[u] = ffma2(av.u[1], wv.u[1], acc8[u]);
            }
        }

        int col = nc + tc;
        if (col < N) {
            float bb = bia[col] + bib[col];
            #pragma unroll
            for (int u = 0; u < 8; ++u)
                g_xg[(m0 + r0 + u) * N + col] = sum2(acc8[u]) + bb;
        }
    }
}

// ---------------------------------------------------------------------------
// LSTM scan (R5 design, best measured) with BT as a parameter.
// W_hh row in registers (packed k-pairs), thread j owns gate row j for all
// BT batches; epilogue re-maps to (b, j) pairs, c in reg.
// Layer 1: BT=4 (128 CTAs). Layers 2/3: BT=2 (256 CTAs, ~2 CTAs/SM,
// half the per-thread FMA chain per step).
// ---------------------------------------------------------------------------
template <int H, int BT, int BLK>
__global__ void __launch_bounds__(BLK, 1)
lstm_scan(const float* __restrict__ whh)
{
    constexpr int G  = 4 * H;
    constexpr int KP = KPad<H>::KP;

    __shared__ float h_s[BT * KP];
    __shared__ float g_s[BT * G];

    const int tid = threadIdx.x;
    const int b0  = blockIdx.x * BT;

    // W row -> registers, packed (k, k+1)
    unsigned long long wreg[KP / 2];
    if (tid < G) {
        const float* wr = whh + tid * H;
        #pragma unroll
        for (int k = 0; k < KP; k += 2) {
            float a = (k     < H) ? wr[k]     : 0.0f;
            float b = (k + 1 < H) ? wr[k + 1] : 0.0f;
            wreg[k / 2] = pack2(a, b);
        }
    }
    for (int i = tid; i < BT * KP; i += BLK) h_s[i] = 0.0f;

    const int eb = (tid < G) ? (tid / H) : 0;   // epilogue pair
    const int ej = tid - eb * H;
    const bool ep = (tid < BT * H);
    float c = 0.0f;

    __syncthreads();

    float nxt[BT];
    if (tid < G) {
        const float* xp = g_xg + (size_t)b0 * G + tid;
        #pragma unroll
        for (int b = 0; b < BT; ++b) nxt[b] = xp[b * G];
    }

    for (int t = 0; t < T_STEPS; ++t) {
        if (tid < G) {
            unsigned long long acc2[BT];
            #pragma unroll
            for (int b = 0; b < BT; ++b) acc2[b] = pack2(nxt[b], 0.0f);

            if (t + 1 < T_STEPS) {
                const float* xq = g_xg + ((size_t)(t + 1) * B_SIZE + b0) * G + tid;
                #pragma unroll
                for (int b = 0; b < BT; ++b) nxt[b] = xq[b * G];
            }

            #pragma unroll
            for (int k = 0; k < KP; k += 4) {
                #pragma unroll
                for (int b = 0; b < BT; ++b) {
                    F4U2 hv = *(const F4U2*)&h_s[b * KP + k];
                    acc2[b] = ffma2(wreg[k / 2],     hv.u[0], acc2[b]);
                    acc2[b] = ffma2(wreg[k / 2 + 1], hv.u[1], acc2[b]);
                }
            }
            #pragma unroll
            for (int b = 0; b < BT; ++b) g_s[b * G + tid] = sum2(acc2[b]);
        }
        __syncthreads();

        if (ep) {
            const float* gp = g_s + eb * G + ej;
            float gi = gp[0];
            float gf = gp[H];
            float gg = gp[2 * H];
            float go = gp[3 * H];
            float cn = sigf(gf) * c + sigf(gi) * tanhf_(gg);
            c = cn;
            float hv = sigf(go) * tanhf_(cn);
            h_s[eb * KP + ej] = hv;
            g_h[((size_t)t * B_SIZE + b0 + eb) * H + ej] = hv;
        }
        __syncthreads();
    }
}

// ---------------------------------------------------------------------------
// Final linear: out[m] = sum_k g_h[m][k] * w[k] + b, K = 25
// ---------------------------------------------------------------------------
__global__ void linear_out(const float* __restrict__ wl,
                           const float* __restrict__ bl,
                           float* __restrict__ out)
{
    __shared__ float sm[256 * H3];
    __shared__ float wsh[H3];
    const int tid = threadIdx.x;
    const size_t base = (size_t)blockIdx.x * 256 * H3;

    for (int idx = tid; idx < 256 * H3; idx += 256) sm[idx] = g_h[base + idx];
    if (tid < H3) wsh[tid] = wl[tid];
    __syncthreads();

    float a = bl[0];
    #pragma unroll
    for (int k = 0; k < H3; ++k) a = fmaf(sm[tid * H3 + k], wsh[k], a);
    out[(size_t)blockIdx.x * 256 + tid] = a;
}

// ---------------------------------------------------------------------------
extern "C" void kernel_launch(void* const* d_in, const int* in_sizes, int n_in,
                              void* d_out, int out_size)
{
    const float* x     = (const float*)d_in[0];
    const float* w_ih1 = (const float*)d_in[1];
    const float* w_hh1 = (const float*)d_in[2];
    const float* b_ih1 = (const float*)d_in[3];
    const float* b_hh1 = (const float*)d_in[4];
    const float* w_ih2 = (const float*)d_in[5];
    const float* w_hh2 = (const float*)d_in[6];
    const float* b_ih2 = (const float*)d_in[7];
    const float* b_hh2 = (const float*)d_in[8];
    const float* w_ih3 = (const float*)d_in[9];
    const float* w_hh3 = (const float*)d_in[10];
    const float* b_ih3 = (const float*)d_in[11];
    const float* b_hh3 = (const float*)d_in[12];
    const float* w_lin = (const float*)d_in[13];
    const float* b_lin = (const float*)d_in[14];
    float* out = (float*)d_out;

    // GEMM dynamic smem sizes: (128 + 64) * KP * 4 bytes
    const int SZ_G1 = 192 * KPad<64>::KP  * 4;   // KP=68  -> 52224
    const int SZ_G2 = 192 * KPad<100>::KP * 4;   // KP=100 -> 76800
    const int SZ_G3 = 192 * KPad<50>::KP  * 4;   // KP=52  -> 39936

    cudaFuncSetAttribute(xg_gemm<64, 400>,  cudaFuncAttributeMaxDynamicSharedMemorySize, SZ_G1);
    cudaFuncSetAttribute(xg_gemm<100, 200>, cudaFuncAttributeMaxDynamicSharedMemorySize, SZ_G2);
    cudaFuncSetAttribute(xg_gemm<50, 100>,  cudaFuncAttributeMaxDynamicSharedMemorySize, SZ_G3);

    const int GRID_M = M_ROWS / 128;  // 2048

    // Layer 1 (scan: BT=4, 128 CTAs, block 416)
    xg_gemm<64, 400><<<GRID_M, 256, SZ_G1>>>(x, w_ih1, b_ih1, b_hh1);
    lstm_scan<100, 4, 416><<<B_SIZE / 4, 416>>>(w_hh1);
    // Layer 2 (scan: BT=2, 256 CTAs, block 224)
    xg_gemm<100, 200><<<GRID_M, 256, SZ_G2>>>(nullptr, w_ih2, b_ih2, b_hh2);
    lstm_scan<50, 2, 224><<<B_SIZE / 2, 224>>>(w_hh2);
    // Layer 3 (scan: BT=2, 256 CTAs, block 128)
    xg_gemm<50, 100><<<GRID_M, 256, SZ_G3>>>(nullptr, w_ih3, b_ih3, b_hh3);
    lstm_scan<25, 2, 128><<<B_SIZE / 2, 128>>>(w_hh3);
    // Output
    linear_out<<<M_ROWS / 256, 256>>>(w_lin, b_lin, out);
}